// round 17
// baseline (speedup 1.0000x reference)
#include <cuda_runtime.h>
#include <cuda_fp16.h>

#define Nn 100000
#define Ee 800000
#define Dd 96
#define SCAN_BLOCKS 98   /* ceil(Nn/1024) */

// fp16 fragment-ordered B: 13 n-tiles x 3 ks-pairs x 32 lanes x 4 u32 (b0,b1 x 2 ks)
#define NFRAG_H (13 * 6 * 32)          /* fragment-generating threads */
#define WF_U32  (13 * 6 * 32 * 2)      /* u32 words in B buffer = 4992 */

// ---------------- scratch (static device globals; no allocation) ----------------
__device__ int   g_srcs[Ee];          // CSR: src per slot
__device__ int2  g_ce[Ee];            // CSR: (dst, exp-weight bits) per slot
__device__ int   g_rowptr[Nn + 1];
__device__ int   g_cursor[Nn];        // degree counts, then fill cursors
__device__ volatile int g_state[SCAN_BLOCKS];   // lookback state: (flag<<20)|value
__device__ __align__(16) __half2 g_hh[Nn * 48]; // h (current layer) fp16, 192B/row
__device__ __align__(16) __half  g_hh1[Nn * 96];// layer-1 output, fp16
__device__ float g_asrc[Nn];
__device__ float g_adst[Nn];
__device__ __align__(16) unsigned g_wf1[WF_U32];  // frag-ordered fp16 W (+alpha tile), layer 1
__device__ __align__(16) unsigned g_wf2[WF_U32];  // layer 2

__device__ __forceinline__ bool ei_is64(const void* ei) {
    const int* w = (const int*)ei;
    return (w[1] == 0 && w[3] == 0 && w[2] == 1);
}
__device__ __forceinline__ void ei_load(const void* ei, bool is64, int i,
                                        int& s, int& d) {
    if (is64) {
        const long long* p = (const long long*)ei;
        s = (int)p[i]; d = (int)p[Ee + i];
    } else {
        const int* p = (const int*)ei;
        s = p[i]; d = p[Ee + i];
    }
}

// ---------------- fused prep: fp16 W-frags both layers + cursor/state reset ---
// m16n8k16 col-major B fragment: lane(g=lane>>2, t=lane&3):
//   b0 = {B[k0+2t][n], B[k0+2t+1][n]}, b1 = {B[k0+2t+8][n], B[k0+2t+9][n]}
// tile 12: col0 = W@a[:96] (g==0), col1 = W@a[96:] (g==1)
__device__ void wprep_one(const float* __restrict__ W, const float* __restrict__ a,
                          unsigned* __restrict__ wf, int fid) {
    int lane = fid & 31;
    int ks   = (fid >> 5) % 6;
    int nt   = fid / (6 * 32);
    int g = lane >> 2, t = lane & 3;
    int k0 = ks * 16 + 2 * t;
    float v0 = 0.f, v1 = 0.f, v2 = 0.f, v3 = 0.f;
    if (nt < 12) {
        int n = nt * 8 + g;
        v0 = __ldg(W + (k0)     * 96 + n);
        v1 = __ldg(W + (k0 + 1) * 96 + n);
        v2 = __ldg(W + (k0 + 8) * 96 + n);
        v3 = __ldg(W + (k0 + 9) * 96 + n);
    } else if (g < 2) {
        const float* av = a + g * 96;
        #pragma unroll 8
        for (int c = 0; c < 96; c++) {
            float wa = __ldg(av + c);
            v0 += __ldg(W + (k0)     * 96 + c) * wa;
            v1 += __ldg(W + (k0 + 1) * 96 + c) * wa;
            v2 += __ldg(W + (k0 + 8) * 96 + c) * wa;
            v3 += __ldg(W + (k0 + 9) * 96 + c) * wa;
        }
    }
    __half2 u0 = __floats2half2_rn(v0, v1);
    __half2 u1 = __floats2half2_rn(v2, v3);
    int idx = ((nt * 3 + (ks >> 1)) * 32 + lane) * 4 + (ks & 1) * 2;
    wf[idx]     = *(unsigned*)&u0;
    wf[idx + 1] = *(unsigned*)&u1;
}

__global__ void k_prep(const float* __restrict__ W1, const float* __restrict__ a1,
                       const float* __restrict__ W2, const float* __restrict__ a2) {
    int i = blockIdx.x * blockDim.x + threadIdx.x;
    if (i < Nn) g_cursor[i] = 0;
    if (i < SCAN_BLOCKS) g_state[i] = 0;
    if (i < NFRAG_H)           wprep_one(W1, a1, g_wf1, i);
    else if (i < 2 * NFRAG_H)  wprep_one(W2, a2, g_wf2, i - NFRAG_H);
}

// ---------------- degree histogram (reads edge_index directly) ----------------
__global__ void k_hist(const void* ei) {
    int i = blockIdx.x * blockDim.x + threadIdx.x;
    bool is64 = ei_is64(ei);
    if (i < Ee) {
        int s, d;
        ei_load(ei, is64, i, s, d);
        atomicAdd(&g_cursor[s], 1);
    }
}

// ---------------- single-pass scan, warp-parallel lookback --------------------
__global__ __launch_bounds__(1024) void k_scan() {
    __shared__ int ws[32];
    __shared__ int s_prefix;
    int bid  = blockIdx.x;
    int i    = bid * 1024 + threadIdx.x;
    int lane = threadIdx.x & 31, wid = threadIdx.x >> 5;
    int deg  = (i < Nn) ? g_cursor[i] : 0;
    int x = deg;
    #pragma unroll
    for (int off = 1; off < 32; off <<= 1) {
        int t = __shfl_up_sync(0xffffffffu, x, off);
        if (lane >= off) x += t;
    }
    if (lane == 31) ws[wid] = x;
    __syncthreads();
    if (wid == 0) {
        int y = ws[lane];
        #pragma unroll
        for (int off = 1; off < 32; off <<= 1) {
            int t = __shfl_up_sync(0xffffffffu, y, off);
            if (lane >= off) y += t;
        }
        ws[lane] = y;
    }
    __syncthreads();
    int incl  = x + (wid > 0 ? ws[wid - 1] : 0);
    int total = ws[31];

    if (wid == 0) {
        if (bid == 0) {
            if (lane == 0) {
                atomicExch((int*)&g_state[0], (2 << 20) | total);
                s_prefix = 0;
            }
        } else {
            if (lane == 0) atomicExch((int*)&g_state[bid], (1 << 20) | total);
            int prefix = 0;
            int p = bid - 1;
            while (true) {
                int idx = p - lane;
                int s = (idx >= 0) ? g_state[idx] : (2 << 20);
                int flag = s >> 20;
                unsigned donem = __ballot_sync(0xffffffffu, flag == 2);
                unsigned zerom = __ballot_sync(0xffffffffu, flag == 0);
                if (donem) {
                    int fd = __ffs(donem) - 1;
                    if ((zerom & ((1u << fd) - 1u)) == 0) {
                        int v = (lane <= fd) ? (s & 0xFFFFF) : 0;
                        #pragma unroll
                        for (int off = 16; off > 0; off >>= 1)
                            v += __shfl_xor_sync(0xffffffffu, v, off);
                        prefix += v;
                        break;
                    }
                } else if (zerom == 0) {
                    int v = s & 0xFFFFF;
                    #pragma unroll
                    for (int off = 16; off > 0; off >>= 1)
                        v += __shfl_xor_sync(0xffffffffu, v, off);
                    prefix += v;
                    p -= 32;
                }
            }
            if (lane == 0) {
                atomicExch((int*)&g_state[bid], (2 << 20) | (prefix + total));
                s_prefix = prefix;
            }
        }
    }
    __syncthreads();
    int prefix = s_prefix;
    if (i < Nn) {
        g_rowptr[i + 1] = prefix + incl;
        g_cursor[i]     = prefix + incl - deg;
    }
    if (i == 0) g_rowptr[0] = 0;
}

// ---------------- CSR fill fused with layer-1 edge weights --------------------
__global__ void k_fill_edge(const void* ei) {
    int i = blockIdx.x * blockDim.x + threadIdx.x;
    bool is64 = ei_is64(ei);
    if (i < Ee) {
        int s, d;
        ei_load(ei, is64, i, s, d);
        int p = atomicAdd(&g_cursor[s], 1);
        g_srcs[p] = s;
        float sm = g_asrc[s] + g_adst[d];
        float l  = (sm > 0.f) ? sm : 0.01f * sm;
        g_ce[p]  = make_int2(d, __float_as_int(__expf(-l)));
    }
}

// ---------------- layer-2 edge weights (CSR order, streaming) -----------------
__global__ void k_edge2() {
    int p = blockIdx.x * blockDim.x + threadIdx.x;
    if (p < Ee) {
        int s = g_srcs[p];
        int d = g_ce[p].x;
        float sm = g_asrc[s] + g_adst[d];
        float l  = (sm > 0.f) ? sm : 0.01f * sm;
        g_ce[p]  = make_int2(d, __float_as_int(__expf(-l)));
    }
}

// ---------------- GEMM: h = X @ W via fp16 mma.m16n8k16 -----------------------
// 128-row tile; A fragments via ldmatrix.x4 (6 per warp); B pre-fragmented.
// smem: X half [128][104] (26624 B) + B frags (19968 B) = 46592 B -> 4 CTAs/SM.
#define SXH 104
#define SMEM_GEMM (128 * SXH * 2 + WF_U32 * 4)

__device__ __forceinline__ uint2 ld_row4h(const float* p) {
    float4 v = *(const float4*)p;
    __half2 h01 = __floats2half2_rn(v.x, v.y);
    __half2 h23 = __floats2half2_rn(v.z, v.w);
    uint2 u;
    u.x = *(unsigned*)&h01;
    u.y = *(unsigned*)&h23;
    return u;
}
__device__ __forceinline__ uint2 ld_row4h(const __half* p) {
    return *(const uint2*)p;
}

#define MMA_H(c, A4, b0, b1)                                                  \
    asm volatile(                                                             \
        "mma.sync.aligned.m16n8k16.row.col.f32.f16.f16.f32 "                  \
        "{%0,%1,%2,%3}, {%4,%5,%6,%7}, {%8,%9}, {%0,%1,%2,%3};"               \
        : "+f"(c[0]), "+f"(c[1]), "+f"(c[2]), "+f"(c[3])                      \
        : "r"((A4)[0]), "r"((A4)[1]), "r"((A4)[2]), "r"((A4)[3]),             \
          "r"(b0), "r"(b1))

template <typename T>
__global__ __launch_bounds__(256, 4) void k_gemm(const T* __restrict__ X,
                                                 const unsigned* __restrict__ WF) {
    extern __shared__ char smem[];
    __half*   sX = (__half*)smem;                       // [128][104]
    unsigned* sB = (unsigned*)(smem + 128 * SXH * 2);   // WF_U32 u32
    int tid  = threadIdx.x;
    int row0 = blockIdx.x * 128;

    // fill X tile as fp16 (3072 4-col chunks)
    #pragma unroll
    for (int i = 0; i < 12; i++) {
        int item = tid + 256 * i;
        int r = item / 24, c4 = item % 24;
        int gr = row0 + r;
        uint2 u = make_uint2(0u, 0u);
        if (gr < Nn) u = ld_row4h(X + gr * 96 + c4 * 4);
        *(uint2*)(sX + r * SXH + c4 * 4) = u;
    }
    // fill B fragments (1248 uint4)
    #pragma unroll
    for (int i = 0; i < 5; i++) {
        int it = tid + 256 * i;
        if (it < WF_U32 / 4) ((uint4*)sB)[it] = ((const uint4*)WF)[it];
    }
    __syncthreads();

    int w = tid >> 5, lane = tid & 31;
    int g = lane >> 2, t = lane & 3;
    int r0 = w * 16;

    // A fragments via ldmatrix.x4: matrix m = lane>>3
    //   m0: rows+0,k+0  m1: rows+8,k+0  m2: rows+0,k+8  m3: rows+8,k+8
    unsigned A[6][4];
    {
        int rowA = r0 + (lane & 7) + ((lane >> 3) & 1) * 8;
        unsigned abase = (unsigned)__cvta_generic_to_shared(sX)
                       + (rowA * SXH + ((lane >> 4) & 1) * 8) * 2;
        #pragma unroll
        for (int ks = 0; ks < 6; ks++) {
            asm volatile(
                "ldmatrix.sync.aligned.m8n8.x4.shared.b16 {%0,%1,%2,%3}, [%4];"
                : "=r"(A[ks][0]), "=r"(A[ks][1]), "=r"(A[ks][2]), "=r"(A[ks][3])
                : "r"(abase + ks * 32));
        }
    }

    int grow_lo = row0 + r0 + g;
    int grow_hi = grow_lo + 8;

    // 6 nt-pairs (tiles 0..11): two independent accumulator chains
    #pragma unroll
    for (int np = 0; np < 6; np++) {
        int ntA = 2 * np, ntB = 2 * np + 1;
        float cA[4] = {0.f, 0.f, 0.f, 0.f};
        float cB[4] = {0.f, 0.f, 0.f, 0.f};
        #pragma unroll
        for (int kp = 0; kp < 3; kp++) {
            uint4 bA = *(const uint4*)(sB + ((ntA * 3 + kp) * 32 + lane) * 4);
            uint4 bB = *(const uint4*)(sB + ((ntB * 3 + kp) * 32 + lane) * 4);
            MMA_H(cA, A[2 * kp],     bA.x, bA.y);
            MMA_H(cB, A[2 * kp],     bB.x, bB.y);
            MMA_H(cA, A[2 * kp + 1], bA.z, bA.w);
            MMA_H(cB, A[2 * kp + 1], bB.z, bB.w);
        }
        int ccA = ntA * 8 + 2 * t, ccB = ntB * 8 + 2 * t;
        if (grow_lo < Nn) {
            g_hh[grow_lo * 48 + (ccA >> 1)] = __floats2half2_rn(cA[0], cA[1]);
            g_hh[grow_lo * 48 + (ccB >> 1)] = __floats2half2_rn(cB[0], cB[1]);
        }
        if (grow_hi < Nn) {
            g_hh[grow_hi * 48 + (ccA >> 1)] = __floats2half2_rn(cA[2], cA[3]);
            g_hh[grow_hi * 48 + (ccB >> 1)] = __floats2half2_rn(cB[2], cB[3]);
        }
    }

    // alpha tile (nt=12): cols 0,1 = (asrc, adst) -> lanes with t==0
    {
        float c[4] = {0.f, 0.f, 0.f, 0.f};
        #pragma unroll
        for (int kp = 0; kp < 3; kp++) {
            uint4 b = *(const uint4*)(sB + ((12 * 3 + kp) * 32 + lane) * 4);
            MMA_H(c, A[2 * kp],     b.x, b.y);
            MMA_H(c, A[2 * kp + 1], b.z, b.w);
        }
        if (t == 0) {
            if (grow_lo < Nn) { g_asrc[grow_lo] = c[0]; g_adst[grow_lo] = c[1]; }
            if (grow_hi < Nn) { g_asrc[grow_hi] = c[2]; g_adst[grow_hi] = c[3]; }
        }
    }
}

// ---------------- edge aggregation: one warp per src node, 4-edge unroll ------
__device__ __forceinline__ void st_row4(float* out, int gw, int lane,
                                        float a0, float a1, float a2, float a3) {
    *(float4*)(out + gw * 96 + lane * 4) = make_float4(a0, a1, a2, a3);
}
__device__ __forceinline__ void st_row4(__half* out, int gw, int lane,
                                        float a0, float a1, float a2, float a3) {
    __half2 lo = __floats2half2_rn(a0, a1);
    __half2 hi = __floats2half2_rn(a2, a3);
    uint2 u;
    u.x = *(unsigned*)&lo;
    u.y = *(unsigned*)&hi;
    *(uint2*)(out + gw * 96 + lane * 4) = u;
}

template <bool RELU, typename OutT>
__global__ __launch_bounds__(256) void k_agg(OutT* __restrict__ out) {
    int gw   = (blockIdx.x * blockDim.x + threadIdx.x) >> 5;
    int lane = threadIdx.x & 31;
    if (gw >= Nn) return;
    int beg = g_rowptr[gw], end = g_rowptr[gw + 1];
    const uint2* H = (const uint2*)g_hh;   // 24 uint2 per row
    float a0 = 0.f, a1 = 0.f, a2 = 0.f, a3 = 0.f, rs = 0.f;
    int j = beg;
    for (; j + 4 <= end; j += 4) {
        int2 c0 = g_ce[j],     c1 = g_ce[j + 1];
        int2 c2 = g_ce[j + 2], c3 = g_ce[j + 3];
        float e0 = __int_as_float(c0.y), e1 = __int_as_float(c1.y);
        float e2 = __int_as_float(c2.y), e3 = __int_as_float(c3.y);
        uint2 h0 = make_uint2(0u, 0u), h1 = make_uint2(0u, 0u);
        uint2 h2 = make_uint2(0u, 0u), h3 = make_uint2(0u, 0u);
        if (lane < 24) {
            h0 = H[c0.x * 24 + lane];
            h1 = H[c1.x * 24 + lane];
            h2 = H[c2.x * 24 + lane];
            h3 = H[c3.x * 24 + lane];
        }
        float2 p0a = __half22float2(*(const __half2*)&h0.x);
        float2 p0b = __half22float2(*(const __half2*)&h0.y);
        float2 p1a = __half22float2(*(const __half2*)&h1.x);
        float2 p1b = __half22float2(*(const __half2*)&h1.y);
        float2 p2a = __half22float2(*(const __half2*)&h2.x);
        float2 p2b = __half22float2(*(const __half2*)&h2.y);
        float2 p3a = __half22float2(*(const __half2*)&h3.x);
        float2 p3b = __half22float2(*(const __half2*)&h3.y);
        a0 += e0 * p0a.x + e1 * p1a.x + e2 * p2a.x + e3 * p3a.x;
        a1 += e0 * p0a.y + e1 * p1a.y + e2 * p2a.y + e3 * p3a.y;
        a2 += e0 * p0b.x + e1 * p1b.x + e2 * p2b.x + e3 * p3b.x;
        a3 += e0 * p0b.y + e1 * p1b.y + e2 * p2b.y + e3 * p3b.y;
        rs += (e0 + e1) + (e2 + e3);
    }
    for (; j < end; j++) {
        int2 ce0 = g_ce[j];
        float e0 = __int_as_float(ce0.y);
        uint2 h0 = make_uint2(0u, 0u);
        if (lane < 24) h0 = H[ce0.x * 24 + lane];
        float2 p0a = __half22float2(*(const __half2*)&h0.x);
        float2 p0b = __half22float2(*(const __half2*)&h0.y);
        a0 += e0 * p0a.x; a1 += e0 * p0a.y;
        a2 += e0 * p0b.x; a3 += e0 * p0b.y;
        rs += e0;
    }
    float inv = (rs > 0.f) ? 1.f / rs : 0.f;
    a0 *= inv; a1 *= inv; a2 *= inv; a3 *= inv;
    if (RELU) {
        a0 = fmaxf(a0, 0.f); a1 = fmaxf(a1, 0.f);
        a2 = fmaxf(a2, 0.f); a3 = fmaxf(a3, 0.f);
    }
    if (lane < 24) st_row4(out, gw, lane, a0, a1, a2, a3);
}

// ---------------- launch ----------------
extern "C" void kernel_launch(void* const* d_in, const int* in_sizes, int n_in,
                              void* d_out, int out_size) {
    const void*  ei = 0;
    const float* x = 0; const float* W1 = 0; const float* a1 = 0;
    const float* W2 = 0; const float* a2 = 0;
    for (int i = 0; i < n_in; i++) {
        int s = in_sizes[i];
        if      (s == 2 * Ee)   ei = d_in[i];
        else if (s == Nn * Dd)  x  = (const float*)d_in[i];
        else if (s == Dd * Dd)  { if (!W1) W1 = (const float*)d_in[i]; else W2 = (const float*)d_in[i]; }
        else if (s == 2 * Dd)   { if (!a1) a1 = (const float*)d_in[i]; else a2 = (const float*)d_in[i]; }
    }
    float* out = (float*)d_out;
    __half* p_h1;     cudaGetSymbolAddress((void**)&p_h1, g_hh1);
    unsigned* p_wf1;  cudaGetSymbolAddress((void**)&p_wf1, g_wf1);
    unsigned* p_wf2;  cudaGetSymbolAddress((void**)&p_wf2, g_wf2);

    cudaFuncSetAttribute(k_gemm<float>,  cudaFuncAttributeMaxDynamicSharedMemorySize, SMEM_GEMM);
    cudaFuncSetAttribute(k_gemm<__half>, cudaFuncAttributeMaxDynamicSharedMemorySize, SMEM_GEMM);

    const int GE = (Ee + 255) / 256;
    const int GN = (Nn + 255) / 256;         // 391 (covers 2*NFRAG_H = 4992 too)
    const int GG = (Nn + 127) / 128;         // 782
    const int GA = (Nn * 32 + 255) / 256;    // 12500

    // prep (wf1+wf2+cursor zero+state reset) + CSR degrees + row offsets
    k_prep<<<GN, 256>>>(W1, a1, W2, a2);
    k_hist<<<GE, 256>>>(ei);
    k_scan<<<SCAN_BLOCKS, 1024>>>();

    // layer 1
    k_gemm<float><<<GG, 256, SMEM_GEMM>>>(x, p_wf1);
    k_fill_edge<<<GE, 256>>>(ei);            // CSR fill + layer-1 edge weights
    k_agg<false, __half><<<GA, 256>>>(p_h1);
    // layer 2
    k_gemm<__half><<<GG, 256, SMEM_GEMM>>>(p_h1, p_wf2);
    k_edge2<<<GE, 256>>>();
    k_agg<true, float><<<GA, 256>>>(out);
}